// round 8
// baseline (speedup 1.0000x reference)
#include <cuda_runtime.h>
#include <cuda_bf16.h>
#include <math.h>

#define Nn 2048
#define Dd 512
#define Rr 4
#define Qq 32
#define Cc 64
#define ALPHA 0.2f
#define EPSLN 1e-5f

// ---------------- scratch (device globals; allocation-free) ----------------
__device__ float g_x[Nn * Dd];
__device__ float g_xenc[Nn * Dd];
__device__ float g_t[Nn * Dd];
__device__ float g_Wh[Rr * Nn * Dd];
__device__ float g_go[Rr * Nn * Dd];
__device__ float g_att[Rr * Nn * Nn];       // unnormalized exp values
__device__ float g_f1[Rr * Nn];
__device__ float g_f2[Rr * Nn];
__device__ float g_inv[Rr * Nn];            // 1/rowsum for deferred softmax norm
__device__ unsigned g_mask[Rr * Nn * (Nn / 32)];  // adj>0 bitmask (2 MB)
__device__ float g_qemb[Dd];
__device__ float g_qproj[Dd];

// ---------------- helpers ----------------
__device__ __forceinline__ unsigned f2tf32(float x) {
    unsigned u;
    asm("cvt.rna.tf32.f32 %0, %1;" : "=r"(u) : "f"(x));
    return u;
}

__device__ __forceinline__ void mma_tf32(float c[4], const unsigned a[4], const unsigned b[2]) {
    asm volatile(
        "mma.sync.aligned.m16n8k8.row.col.f32.tf32.tf32.f32 "
        "{%0,%1,%2,%3}, {%4,%5,%6,%7}, {%8,%9}, {%0,%1,%2,%3};"
        : "+f"(c[0]), "+f"(c[1]), "+f"(c[2]), "+f"(c[3])
        : "r"(a[0]), "r"(a[1]), "r"(a[2]), "r"(a[3]), "r"(b[0]), "r"(b[1]));
}

__device__ __forceinline__ float block_sum256(float v, float* sbuf) {
    __syncthreads();
    #pragma unroll
    for (int o = 16; o > 0; o >>= 1) v += __shfl_xor_sync(0xffffffffu, v, o);
    if ((threadIdx.x & 31) == 0) sbuf[threadIdx.x >> 5] = v;
    __syncthreads();
    float tot = 0.f;
    #pragma unroll
    for (int i = 0; i < 8; ++i) tot += sbuf[i];
    return tot;
}

__device__ __forceinline__ float block_max256(float v, float* sbuf) {
    __syncthreads();
    #pragma unroll
    for (int o = 16; o > 0; o >>= 1) v = fmaxf(v, __shfl_xor_sync(0xffffffffu, v, o));
    if ((threadIdx.x & 31) == 0) sbuf[threadIdx.x >> 5] = v;
    __syncthreads();
    float tot = -INFINITY;
    #pragma unroll
    for (int i = 0; i < 8; ++i) tot = fmaxf(tot, sbuf[i]);
    return tot;
}

// ---------------- tf32 tensor-core GEMM v2 ----------------
// 128x128x16 CTA tile, 8 warps (32x64 warp tile), 2-stage smem double buffer,
// paired-k uint2 smem layout: slot[s][col] = (k = base+s%4 [+8 if s>=4], k+4)
// => fragment fetch is LDS.64 (half the instruction count of scalar).
// C[M,N] = A[M,K] * B.  TRANSB=0: B is [K,N] row-major. TRANSB=1: B is [N,K] row-major.
template <int TRANSB>
__global__ void __launch_bounds__(256, 2) mma_gemm(
    const float* __restrict__ A, const float* __restrict__ B, float* __restrict__ C,
    int M, int N, int K, long sA, long sB, long sC)
{
    A += (long)blockIdx.z * sA;
    B += (long)blockIdx.z * sB;
    C += (long)blockIdx.z * sC;

    __shared__ uint2 As[2][8][132];
    __shared__ uint2 Bs[2][8][132];

    const int t = threadIdx.x, lane = t & 31, wid = t >> 5;
    const int bm = blockIdx.y * 128, bn = blockIdx.x * 128;
    const int wm = (wid & 3) * 32, wn = (wid >> 2) * 64;
    const int kl = lane & 3, gm = lane >> 2;

    float acc[2][8][4];
    #pragma unroll
    for (int mi = 0; mi < 2; ++mi)
        #pragma unroll
        for (int ni = 0; ni < 8; ++ni)
            #pragma unroll
            for (int c = 0; c < 4; ++c) acc[mi][ni][c] = 0.f;

    // A-side load map (also used for B when TRANSB=1): float4 along K
    const int rowA0 = t >> 2;              // 0..63 (and +64)
    const int kqA  = (t & 3) * 4;          // 0,4,8,12
    const int sbA  = (kqA & 8) ? 4 : 0;    // pair-slot base
    const int cpA  = (kqA >> 2) & 1;       // component (x/y)
    // B-side load map (TRANSB=0): float4 along N
    const int kB0 = t >> 5;                // 0..7
    const int nqB = (t & 31) * 4;
    const int sbB = kB0 & 3;
    const int cpB = (kB0 >> 2) & 1;

    float4 fa0, fa1, fb0, fb1;

    #define LOAD_TILE(k0)                                                          \
        fa0 = *(const float4*)(A + (long)(bm + rowA0) * K + (k0) + kqA);           \
        fa1 = *(const float4*)(A + (long)(bm + rowA0 + 64) * K + (k0) + kqA);      \
        if (TRANSB) {                                                              \
            fb0 = *(const float4*)(B + (long)(bn + rowA0) * K + (k0) + kqA);       \
            fb1 = *(const float4*)(B + (long)(bn + rowA0 + 64) * K + (k0) + kqA);  \
        } else {                                                                   \
            fb0 = *(const float4*)(B + (long)((k0) + kB0) * N + bn + nqB);         \
            fb1 = *(const float4*)(B + (long)((k0) + kB0 + 8) * N + bn + nqB);     \
        }

    #define STORE_TILE(st)                                                         \
        {                                                                          \
            unsigned* pa = (unsigned*)&As[st][sbA][0] + rowA0 * 2 + cpA;           \
            pa[0]   = f2tf32(fa0.x);  pa[264] = f2tf32(fa0.y);                     \
            pa[528] = f2tf32(fa0.z);  pa[792] = f2tf32(fa0.w);                     \
            unsigned* pa2 = pa + 128;                                              \
            pa2[0]   = f2tf32(fa1.x);  pa2[264] = f2tf32(fa1.y);                   \
            pa2[528] = f2tf32(fa1.z);  pa2[792] = f2tf32(fa1.w);                   \
            if (TRANSB) {                                                          \
                unsigned* pb = (unsigned*)&Bs[st][sbA][0] + rowA0 * 2 + cpA;       \
                pb[0]   = f2tf32(fb0.x);  pb[264] = f2tf32(fb0.y);                 \
                pb[528] = f2tf32(fb0.z);  pb[792] = f2tf32(fb0.w);                 \
                unsigned* pb2 = pb + 128;                                          \
                pb2[0]   = f2tf32(fb1.x);  pb2[264] = f2tf32(fb1.y);               \
                pb2[528] = f2tf32(fb1.z);  pb2[792] = f2tf32(fb1.w);               \
            } else {                                                               \
                unsigned* pb = (unsigned*)&Bs[st][sbB][0] + nqB * 2 + cpB;         \
                pb[0] = f2tf32(fb0.x); pb[2] = f2tf32(fb0.y);                      \
                pb[4] = f2tf32(fb0.z); pb[6] = f2tf32(fb0.w);                      \
                unsigned* pb2 = pb + 4 * 264;                                      \
                pb2[0] = f2tf32(fb1.x); pb2[2] = f2tf32(fb1.y);                    \
                pb2[4] = f2tf32(fb1.z); pb2[6] = f2tf32(fb1.w);                    \
            }                                                                      \
        }

    // prologue: stage tile 0
    LOAD_TILE(0);
    STORE_TILE(0);
    __syncthreads();

    int st = 0;
    for (int k0 = 0; k0 < K; k0 += 16) {
        const bool more = (k0 + 16 < K);
        if (more) { LOAD_TILE(k0 + 16); }

        // compute from stage st: 2 k8 steps, LDS.64 fragments
        #pragma unroll
        for (int kb = 0; kb < 2; ++kb) {
            const int so = kb * 4 + kl;
            uint2 a0[2], a1[2], bv[8];
            #pragma unroll
            for (int mi = 0; mi < 2; ++mi) {
                int m = wm + mi * 16 + gm;
                a0[mi] = As[st][so][m];
                a1[mi] = As[st][so][m + 8];
            }
            #pragma unroll
            for (int ni = 0; ni < 8; ++ni)
                bv[ni] = Bs[st][so][wn + ni * 8 + gm];
            #pragma unroll
            for (int mi = 0; mi < 2; ++mi) {
                unsigned a[4] = {a0[mi].x, a1[mi].x, a0[mi].y, a1[mi].y};
                #pragma unroll
                for (int ni = 0; ni < 8; ++ni) {
                    unsigned b[2] = {bv[ni].x, bv[ni].y};
                    mma_tf32(acc[mi][ni], a, b);
                }
            }
        }

        if (more) {
            STORE_TILE(st ^ 1);
            st ^= 1;
            __syncthreads();
        }
    }

    // epilogue
    #pragma unroll
    for (int mi = 0; mi < 2; ++mi) {
        int row0 = bm + wm + mi * 16 + gm;
        #pragma unroll
        for (int ni = 0; ni < 8; ++ni) {
            int col = bn + wn + ni * 8 + kl * 2;
            *(float2*)(C + (long)row0 * N + col) = make_float2(acc[mi][ni][0], acc[mi][ni][1]);
            *(float2*)(C + (long)(row0 + 8) * N + col) = make_float2(acc[mi][ni][2], acc[mi][ni][3]);
        }
    }
    #undef LOAD_TILE
    #undef STORE_TILE
}

// ---------------- pack adj -> bitmask ----------------
__global__ void pack_adj_kernel(const int* __restrict__ adj, unsigned* __restrict__ mask)
{
    const int row = blockIdx.x;          // Rr*Nn rows
    const int lane = threadIdx.x & 31, w = threadIdx.x >> 5;   // 256 threads
    const int* arow = adj + (long)row * Nn;
    for (int wi = w; wi < Nn / 32; wi += 8) {
        unsigned b = __ballot_sync(0xffffffffu, arow[wi * 32 + lane] > 0);
        if (lane == 0) mask[(long)row * (Nn / 32) + wi] = b;
    }
}

// ---------------- question layer: qemb + qproj ----------------
__global__ void question_kernel(const float* __restrict__ qe, const float* __restrict__ wq,
                                const float* __restrict__ Wqc, const float* __restrict__ bqc,
                                float* __restrict__ qemb, float* __restrict__ qproj)
{
    __shared__ float logits[Qq];
    __shared__ float sc[Qq];
    __shared__ float marr[Dd];
    const int t = threadIdx.x;          // 512
    const int w = t >> 5, lane = t & 31;

    for (int q = w; q < Qq; q += 16) {
        float s = 0.f;
        for (int d = lane; d < Dd; d += 32) s += qe[q * Dd + d] * wq[d];
        #pragma unroll
        for (int o = 16; o > 0; o >>= 1) s += __shfl_xor_sync(0xffffffffu, s, o);
        if (lane == 0) logits[q] = s;
    }
    __syncthreads();
    if (w == 0) {
        float v = logits[lane];
        float mx = v;
        #pragma unroll
        for (int o = 16; o > 0; o >>= 1) mx = fmaxf(mx, __shfl_xor_sync(0xffffffffu, mx, o));
        float ex = __expf(v - mx);
        float sum = ex;
        #pragma unroll
        for (int o = 16; o > 0; o >>= 1) sum += __shfl_xor_sync(0xffffffffu, sum, o);
        sc[lane] = ex / sum;
    }
    __syncthreads();
    {
        float acc = 0.f, msum = 0.f;
        #pragma unroll 4
        for (int q = 0; q < Qq; ++q) { float v = qe[q * Dd + t]; acc += sc[q] * v; msum += v; }
        qemb[t] = acc;
        marr[t] = msum * (1.f / (float)Qq);
    }
    __syncthreads();
    {
        float acc = bqc[t];
        for (int d = 0; d < Dd; ++d) acc += marr[d] * Wqc[d * Dd + t];
        qproj[t] = acc;
    }
}

// ---------------- gate ----------------
__global__ void gate_kernel(const float* __restrict__ x_in, const float* __restrict__ tmat,
                            const float* __restrict__ bc, const float* __restrict__ qemb,
                            float* __restrict__ xout)
{
    __shared__ float sbuf[8];
    const int n = blockIdx.x, t = threadIdx.x;   // 256
    const float* trow = tmat + (long)n * Dd;
    float s = 0.f;
    for (int d = t; d < Dd; d += 256) s += (trow[d] + bc[d]) * qemb[d];
    s = block_sum256(s, sbuf);
    float p = 1.f / (1.f + __expf(-s));
    const float* xrow = x_in + (long)n * Dd;
    float* orow = xout + (long)n * Dd;
    for (int d = t; d < Dd; d += 256) orow[d] = p * xrow[d] + (1.f - p) * qemb[d];
}

// ---------------- f1/f2 = Wh · a1/a2 ----------------
__global__ void f12_kernel(const float* __restrict__ Wh, const float* __restrict__ a1,
                           const float* __restrict__ a2, float* __restrict__ f1,
                           float* __restrict__ f2)
{
    __shared__ float sbuf[8];
    const int rn = blockIdx.x;
    const int r  = rn >> 11;
    const float* row = Wh + (long)rn * Dd;
    const float* p1 = a1 + r * Dd;
    const float* p2 = a2 + r * Dd;
    float s1 = 0.f, s2 = 0.f;
    for (int d = threadIdx.x; d < Dd; d += 256) {
        float v = row[d];
        s1 += v * p1[d];
        s2 += v * p2[d];
    }
    s1 = block_sum256(s1, sbuf);
    s2 = block_sum256(s2, sbuf);
    if (threadIdx.x == 0) { f1[rn] = s1; f2[rn] = s2; }
}

// ---------------- masked softmax row (unnormalized exp + invsum) ----------------
__global__ void att_kernel(const float* __restrict__ f1, const float* __restrict__ f2,
                           const unsigned* __restrict__ mask, float* __restrict__ att,
                           float* __restrict__ invs)
{
    __shared__ float sbuf[8];
    const int rn = blockIdx.x;
    const int r  = rn >> 11;
    const unsigned* mrow = mask + (long)rn * (Nn / 32);
    float* orow = att + (long)rn * Nn;
    const float f1v = f1[rn];
    const float* f2r = f2 + r * Nn;
    const int t = threadIdx.x;   // 256, 8 elems each

    float e[8];
    float mx = -INFINITY;
    #pragma unroll
    for (int i = 0; i < 8; ++i) {
        int m = t + i * 256;
        float v = f1v + f2r[m];
        v = v > 0.f ? v : ALPHA * v;
        unsigned bit = (mrow[m >> 5] >> (m & 31)) & 1u;
        e[i] = bit ? v : -1e30f;
        mx = fmaxf(mx, e[i]);
    }
    mx = block_max256(mx, sbuf);

    float sum = 0.f;
    float ex[8];
    #pragma unroll
    for (int i = 0; i < 8; ++i) {
        ex[i] = __expf(e[i] - mx);
        sum += ex[i];
    }
    sum = block_sum256(sum, sbuf);
    #pragma unroll
    for (int i = 0; i < 8; ++i) orow[t + i * 256] = ex[i];
    if (t == 0) invs[rn] = 1.f / sum;
}

// ---------------- scale + elu (+ optional LayerNorm) + max over relations ----------------
__global__ void postproc_kernel(const float* __restrict__ go, float* __restrict__ xout,
                                const float* __restrict__ g, const float* __restrict__ b,
                                const float* __restrict__ invs, int do_ln)
{
    __shared__ float sbuf[8];
    const int n = blockIdx.x, t = threadIdx.x;   // 256 threads, 2 feats each
    float m0 = -INFINITY, m1 = -INFINITY;
    for (int r = 0; r < Rr; ++r) {
        const float inv = invs[r * Nn + n];
        const float* row = go + (long)(r * Nn + n) * Dd;
        float v0 = row[t] * inv, v1 = row[t + 256] * inv;
        v0 = v0 > 0.f ? v0 : __expf(v0) - 1.f;
        v1 = v1 > 0.f ? v1 : __expf(v1) - 1.f;
        if (do_ln) {
            float s = block_sum256(v0 + v1, sbuf);
            float mu = s * (1.f / (float)Dd);
            float d0 = v0 - mu, d1 = v1 - mu;
            float q = block_sum256(d0 * d0 + d1 * d1, sbuf);
            float ivn = rsqrtf(q * (1.f / (float)Dd) + EPSLN);
            v0 = d0 * ivn * g[t] + b[t];
            v1 = d1 * ivn * g[t + 256] + b[t + 256];
        }
        m0 = fmaxf(m0, v0);
        m1 = fmaxf(m1, v1);
    }
    xout[(long)n * Dd + t] = m0;
    xout[(long)n * Dd + t + 256] = m1;
}

__global__ void copy_kernel(float* __restrict__ dst, const float* __restrict__ src)
{
    int i = blockIdx.x * 256 + threadIdx.x;
    dst[i] = src[i];
}

// ---------------- choice layer ----------------
__global__ void choice_kernel(const float* __restrict__ xenc, const int* __restrict__ cidx,
                              const float* __restrict__ qproj, const float* __restrict__ Wout,
                              const float* __restrict__ bout, float* __restrict__ out)
{
    __shared__ float sc[5][Cc];
    __shared__ float dw[5][Cc];
    __shared__ float lg[5];
    const int t = threadIdx.x;       // 512
    const int w = t >> 5, lane = t & 31;

    for (int p = w; p < 5 * Cc; p += 16) {
        int node = cidx[p];
        const float* row = xenc + (long)node * Dd;
        float s1 = 0.f, s2 = 0.f;
        for (int d = lane; d < Dd; d += 32) {
            float v = row[d];
            s1 += v * qproj[d];
            s2 += v * Wout[d];
        }
        #pragma unroll
        for (int o = 16; o > 0; o >>= 1) {
            s1 += __shfl_xor_sync(0xffffffffu, s1, o);
            s2 += __shfl_xor_sync(0xffffffffu, s2, o);
        }
        if (lane == 0) { sc[p / Cc][p % Cc] = s1; dw[p / Cc][p % Cc] = s2; }
    }
    __syncthreads();
    if (w < 5) {
        float v0 = sc[w][lane], v1 = sc[w][lane + 32];
        float mx = fmaxf(v0, v1);
        #pragma unroll
        for (int o = 16; o > 0; o >>= 1) mx = fmaxf(mx, __shfl_xor_sync(0xffffffffu, mx, o));
        float e0 = __expf(v0 - mx), e1 = __expf(v1 - mx);
        float s = e0 + e1;
        float l = e0 * dw[w][lane] + e1 * dw[w][lane + 32];
        #pragma unroll
        for (int o = 16; o > 0; o >>= 1) {
            s += __shfl_xor_sync(0xffffffffu, s, o);
            l += __shfl_xor_sync(0xffffffffu, l, o);
        }
        if (lane == 0) lg[w] = l / s + bout[0];
    }
    __syncthreads();
    if (t == 0) {
        float mx = lg[0];
        #pragma unroll
        for (int k = 1; k < 5; ++k) mx = fmaxf(mx, lg[k]);
        float sum = 0.f;
        #pragma unroll
        for (int k = 0; k < 5; ++k) sum += __expf(lg[k] - mx);
        float lse = mx + logf(sum);
        #pragma unroll
        for (int k = 0; k < 5; ++k) out[k] = lg[k] - lse;
    }
}

// ---------------- launcher ----------------
extern "C" void kernel_launch(void* const* d_in, const int* in_sizes, int n_in,
                              void* d_out, int out_size)
{
    const float* x    = (const float*)d_in[0];
    const int*   adj  = (const int*)  d_in[1];
    const float* qe   = (const float*)d_in[2];
    const int*   cidx = (const int*)  d_in[4];
    const float* Wc   = (const float*)d_in[5];
    const float* bc   = (const float*)d_in[6];
    const float* wq   = (const float*)d_in[7];
    const float* encW = (const float*)d_in[8];
    const float* ea1  = (const float*)d_in[9];
    const float* ea2  = (const float*)d_in[10];
    const float* decW = (const float*)d_in[11];
    const float* da1  = (const float*)d_in[12];
    const float* da2  = (const float*)d_in[13];
    const float* lng  = (const float*)d_in[14];
    const float* lnb  = (const float*)d_in[15];
    const float* Wqc  = (const float*)d_in[16];
    const float* bqc  = (const float*)d_in[17];
    const float* Wout = (const float*)d_in[18];
    const float* bout = (const float*)d_in[19];
    float* out = (float*)d_out;

    float *px, *pxenc, *pt, *pWh, *patt, *pgo, *pf1, *pf2, *pinv, *pqemb, *pqproj;
    unsigned* pmask;
    cudaGetSymbolAddress((void**)&px,     g_x);
    cudaGetSymbolAddress((void**)&pxenc,  g_xenc);
    cudaGetSymbolAddress((void**)&pt,     g_t);
    cudaGetSymbolAddress((void**)&pWh,    g_Wh);
    cudaGetSymbolAddress((void**)&patt,   g_att);
    cudaGetSymbolAddress((void**)&pgo,    g_go);
    cudaGetSymbolAddress((void**)&pf1,    g_f1);
    cudaGetSymbolAddress((void**)&pf2,    g_f2);
    cudaGetSymbolAddress((void**)&pinv,   g_inv);
    cudaGetSymbolAddress((void**)&pmask,  g_mask);
    cudaGetSymbolAddress((void**)&pqemb,  g_qemb);
    cudaGetSymbolAddress((void**)&pqproj, g_qproj);

    // 0) pack adjacency to bitmask (reused by all 4 layers)
    pack_adj_kernel<<<Rr * Nn, 256>>>(adj, pmask);

    // 1) question layer
    question_kernel<<<1, 512>>>(qe, wq, Wqc, bqc, pqemb, pqproj);

    // 2) gate: t = x @ Wc^T (NT), then elementwise gate
    mma_gemm<1><<<dim3(Dd / 128, Nn / 128, 1), 256>>>(x, Wc, pt, Nn, Dd, Dd, 0, 0, 0);
    gate_kernel<<<Nn, 256>>>(x, pt, bc, pqemb, px);

    // 3) encoder: 2 heads, LN + max
    for (int h = 0; h < 2; ++h) {
        mma_gemm<0><<<dim3(Dd / 128, Nn / 128, Rr), 256>>>(
            px, encW + (long)h * Rr * Dd * Dd, pWh, Nn, Dd, Dd,
            0, (long)Dd * Dd, (long)Nn * Dd);
        f12_kernel<<<Rr * Nn, 256>>>(pWh, ea1 + h * Rr * Dd, ea2 + h * Rr * Dd, pf1, pf2);
        att_kernel<<<Rr * Nn, 256>>>(pf1, pf2, pmask, patt, pinv);
        mma_gemm<0><<<dim3(Dd / 128, Nn / 128, Rr), 256>>>(
            patt, pWh, pgo, Nn, Dd, Nn,
            (long)Nn * Nn, (long)Nn * Dd, (long)Nn * Dd);
        postproc_kernel<<<Nn, 256>>>(pgo, px, lng, lnb, pinv, 1);
    }
    copy_kernel<<<Nn * Dd / 256, 256>>>(pxenc, px);

    // 4) decoder: 2 heads, LN only on first, write final xd straight to output
    float* xdout = (out_size >= 5 + Nn * Dd) ? (out + 5) : px;
    for (int i = 0; i < 2; ++i) {
        mma_gemm<0><<<dim3(Dd / 128, Nn / 128, Rr), 256>>>(
            px, decW + (long)i * Rr * Dd * Dd, pWh, Nn, Dd, Dd,
            0, (long)Dd * Dd, (long)Nn * Dd);
        f12_kernel<<<Rr * Nn, 256>>>(pWh, da1 + i * Rr * Dd, da2 + i * Rr * Dd, pf1, pf2);
        att_kernel<<<Rr * Nn, 256>>>(pf1, pf2, pmask, patt, pinv);
        mma_gemm<0><<<dim3(Dd / 128, Nn / 128, Rr), 256>>>(
            patt, pWh, pgo, Nn, Dd, Nn,
            (long)Nn * Nn, (long)Nn * Dd, (long)Nn * Dd);
        postproc_kernel<<<Nn, 256>>>(pgo, (i == 1) ? xdout : px, lng, lnb, pinv, (i == 0) ? 1 : 0);
    }

    // 5) choice layer -> out[0..4]
    choice_kernel<<<1, 512>>>(pxenc, cidx, pqproj, Wout, bout, out);
}

// round 9
// speedup vs baseline: 1.5536x; 1.5536x over previous
#include <cuda_runtime.h>
#include <cuda_fp16.h>
#include <cuda_bf16.h>
#include <math.h>

#define Nn 2048
#define Dd 512
#define Rr 4
#define Qq 32
#define Cc 64
#define ALPHA 0.2f
#define EPSLN 1e-5f

// ---------------- scratch (device globals; allocation-free) ----------------
__device__ float g_x[Nn * Dd];
__device__ float g_xenc[Nn * Dd];
__device__ float g_t[Nn * Dd];
__device__ float g_Wh[Rr * Nn * Dd];
__device__ float g_go[Rr * Nn * Dd];
__device__ float g_att[Rr * Nn * Nn];       // unnormalized exp values
__device__ float g_f1[Rr * Nn];
__device__ float g_f2[Rr * Nn];
__device__ float g_inv[Rr * Nn];            // 1/rowsum for deferred softmax norm
__device__ unsigned g_mask[Rr * Nn * (Nn / 32)];  // adj>0 bitmask (2 MB)
__device__ float g_qemb[Dd];
__device__ float g_qproj[Dd];

// ---------------- helpers ----------------
__device__ __forceinline__ unsigned pack_h2(float x, float y) {
    __half2 h = __floats2half2_rn(x, y);
    return *reinterpret_cast<unsigned*>(&h);
}

__device__ __forceinline__ void mma_f16(float c[4], const unsigned a[4], const unsigned b[2]) {
    asm volatile(
        "mma.sync.aligned.m16n8k16.row.col.f32.f16.f16.f32 "
        "{%0,%1,%2,%3}, {%4,%5,%6,%7}, {%8,%9}, {%0,%1,%2,%3};"
        : "+f"(c[0]), "+f"(c[1]), "+f"(c[2]), "+f"(c[3])
        : "r"(a[0]), "r"(a[1]), "r"(a[2]), "r"(a[3]), "r"(b[0]), "r"(b[1]));
}

__device__ __forceinline__ float block_sum256(float v, float* sbuf) {
    __syncthreads();
    #pragma unroll
    for (int o = 16; o > 0; o >>= 1) v += __shfl_xor_sync(0xffffffffu, v, o);
    if ((threadIdx.x & 31) == 0) sbuf[threadIdx.x >> 5] = v;
    __syncthreads();
    float tot = 0.f;
    #pragma unroll
    for (int i = 0; i < 8; ++i) tot += sbuf[i];
    return tot;
}

__device__ __forceinline__ float block_max256(float v, float* sbuf) {
    __syncthreads();
    #pragma unroll
    for (int o = 16; o > 0; o >>= 1) v = fmaxf(v, __shfl_xor_sync(0xffffffffu, v, o));
    if ((threadIdx.x & 31) == 0) sbuf[threadIdx.x >> 5] = v;
    __syncthreads();
    float tot = -INFINITY;
    #pragma unroll
    for (int i = 0; i < 8; ++i) tot = fmaxf(tot, sbuf[i]);
    return tot;
}

// ---------------- f16 tensor-core GEMM v3 ----------------
// 128x128x16 CTA tile, 8 warps (32x64 warp tile), single-stage (v1 structure),
// m16n8k16 f16 MMA (fp32 accum). smem packs (k,k+1) pairs as half2:
//   As[kp][m] = (A[m][2kp], A[m][2kp+1]), kp = 0..7, stride 136 -> conflict-free
//   fragment banks (8*kl + gm) all-distinct per warp.
// f16 mantissa (10+1 bits) == tf32 mantissa -> same accuracy as R5 tf32 kernel.
// C[M,N] = A[M,K] * B.  TRANSB=0: B is [K,N] row-major. TRANSB=1: B is [N,K] row-major.
template <int TRANSB>
__global__ void __launch_bounds__(256, 2) mma_gemm(
    const float* __restrict__ A, const float* __restrict__ B, float* __restrict__ C,
    int M, int N, int K, long sA, long sB, long sC)
{
    A += (long)blockIdx.z * sA;
    B += (long)blockIdx.z * sB;
    C += (long)blockIdx.z * sC;

    __shared__ unsigned As[8][136];   // half2-packed
    __shared__ unsigned Bs[8][136];

    const int t = threadIdx.x, lane = t & 31, wid = t >> 5;
    const int bm = blockIdx.y * 128, bn = blockIdx.x * 128;
    const int wm = (wid & 3) * 32, wn = (wid >> 2) * 64;
    const int kl = lane & 3, gm = lane >> 2;

    float acc[2][8][4];
    #pragma unroll
    for (int mi = 0; mi < 2; ++mi)
        #pragma unroll
        for (int ni = 0; ni < 8; ++ni)
            #pragma unroll
            for (int c = 0; c < 4; ++c) acc[mi][ni][c] = 0.f;

    // A-side (and B when TRANSB=1): float4 along K
    const int rowA0 = t >> 2;            // 0..63 (and +64)
    const int kqA  = (t & 3) * 4;        // 0,4,8,12
    const int sA0  = kqA >> 1;           // half2 slot: 0,2,4,6
    // B-side (TRANSB=0): two float4 rows (2kpB, 2kpB+1), 4 packed half2 along N
    const int kpB = t >> 5;              // 0..7
    const int nqB = (t & 31) * 4;

    float4 fa0, fa1, fb0, fb1;
    fa0 = *(const float4*)(A + (long)(bm + rowA0) * K + kqA);
    fa1 = *(const float4*)(A + (long)(bm + rowA0 + 64) * K + kqA);
    if (TRANSB) {
        fb0 = *(const float4*)(B + (long)(bn + rowA0) * K + kqA);
        fb1 = *(const float4*)(B + (long)(bn + rowA0 + 64) * K + kqA);
    } else {
        fb0 = *(const float4*)(B + (long)(2 * kpB) * N + bn + nqB);
        fb1 = *(const float4*)(B + (long)(2 * kpB + 1) * N + bn + nqB);
    }

    for (int k0 = 0; k0 < K; k0 += 16) {
        // stage current tile (convert to packed f16 pairs)
        As[sA0 + 0][rowA0]      = pack_h2(fa0.x, fa0.y);
        As[sA0 + 1][rowA0]      = pack_h2(fa0.z, fa0.w);
        As[sA0 + 0][rowA0 + 64] = pack_h2(fa1.x, fa1.y);
        As[sA0 + 1][rowA0 + 64] = pack_h2(fa1.z, fa1.w);
        if (TRANSB) {
            Bs[sA0 + 0][rowA0]      = pack_h2(fb0.x, fb0.y);
            Bs[sA0 + 1][rowA0]      = pack_h2(fb0.z, fb0.w);
            Bs[sA0 + 0][rowA0 + 64] = pack_h2(fb1.x, fb1.y);
            Bs[sA0 + 1][rowA0 + 64] = pack_h2(fb1.z, fb1.w);
        } else {
            uint4 bp;
            bp.x = pack_h2(fb0.x, fb1.x);
            bp.y = pack_h2(fb0.y, fb1.y);
            bp.z = pack_h2(fb0.z, fb1.z);
            bp.w = pack_h2(fb0.w, fb1.w);
            *(uint4*)&Bs[kpB][nqB] = bp;
        }
        __syncthreads();

        // prefetch next tile
        if (k0 + 16 < K) {
            int kn = k0 + 16;
            fa0 = *(const float4*)(A + (long)(bm + rowA0) * K + kn + kqA);
            fa1 = *(const float4*)(A + (long)(bm + rowA0 + 64) * K + kn + kqA);
            if (TRANSB) {
                fb0 = *(const float4*)(B + (long)(bn + rowA0) * K + kn + kqA);
                fb1 = *(const float4*)(B + (long)(bn + rowA0 + 64) * K + kn + kqA);
            } else {
                fb0 = *(const float4*)(B + (long)(kn + 2 * kpB) * N + bn + nqB);
                fb1 = *(const float4*)(B + (long)(kn + 2 * kpB + 1) * N + bn + nqB);
            }
        }

        // compute: one m16n8k16 step per (mi, ni)
        {
            unsigned a[2][4], bv[8][2];
            #pragma unroll
            for (int mi = 0; mi < 2; ++mi) {
                int m = wm + mi * 16 + gm;
                a[mi][0] = As[kl][m];
                a[mi][1] = As[kl][m + 8];
                a[mi][2] = As[kl + 4][m];
                a[mi][3] = As[kl + 4][m + 8];
            }
            #pragma unroll
            for (int ni = 0; ni < 8; ++ni) {
                int n = wn + ni * 8 + gm;
                bv[ni][0] = Bs[kl][n];
                bv[ni][1] = Bs[kl + 4][n];
            }
            #pragma unroll
            for (int mi = 0; mi < 2; ++mi)
                #pragma unroll
                for (int ni = 0; ni < 8; ++ni)
                    mma_f16(acc[mi][ni], a[mi], bv[ni]);
        }
        __syncthreads();
    }

    // epilogue (same fragment->C mapping as tf32 version)
    #pragma unroll
    for (int mi = 0; mi < 2; ++mi) {
        int row0 = bm + wm + mi * 16 + gm;
        #pragma unroll
        for (int ni = 0; ni < 8; ++ni) {
            int col = bn + wn + ni * 8 + kl * 2;
            *(float2*)(C + (long)row0 * N + col) = make_float2(acc[mi][ni][0], acc[mi][ni][1]);
            *(float2*)(C + (long)(row0 + 8) * N + col) = make_float2(acc[mi][ni][2], acc[mi][ni][3]);
        }
    }
}

// ---------------- pack adj -> bitmask ----------------
__global__ void pack_adj_kernel(const int* __restrict__ adj, unsigned* __restrict__ mask)
{
    const int row = blockIdx.x;          // Rr*Nn rows
    const int lane = threadIdx.x & 31, w = threadIdx.x >> 5;   // 256 threads
    const int* arow = adj + (long)row * Nn;
    for (int wi = w; wi < Nn / 32; wi += 8) {
        unsigned b = __ballot_sync(0xffffffffu, arow[wi * 32 + lane] > 0);
        if (lane == 0) mask[(long)row * (Nn / 32) + wi] = b;
    }
}

// ---------------- question layer: qemb + qproj ----------------
__global__ void question_kernel(const float* __restrict__ qe, const float* __restrict__ wq,
                                const float* __restrict__ Wqc, const float* __restrict__ bqc,
                                float* __restrict__ qemb, float* __restrict__ qproj)
{
    __shared__ float logits[Qq];
    __shared__ float sc[Qq];
    __shared__ float marr[Dd];
    const int t = threadIdx.x;          // 512
    const int w = t >> 5, lane = t & 31;

    for (int q = w; q < Qq; q += 16) {
        float s = 0.f;
        for (int d = lane; d < Dd; d += 32) s += qe[q * Dd + d] * wq[d];
        #pragma unroll
        for (int o = 16; o > 0; o >>= 1) s += __shfl_xor_sync(0xffffffffu, s, o);
        if (lane == 0) logits[q] = s;
    }
    __syncthreads();
    if (w == 0) {
        float v = logits[lane];
        float mx = v;
        #pragma unroll
        for (int o = 16; o > 0; o >>= 1) mx = fmaxf(mx, __shfl_xor_sync(0xffffffffu, mx, o));
        float ex = __expf(v - mx);
        float sum = ex;
        #pragma unroll
        for (int o = 16; o > 0; o >>= 1) sum += __shfl_xor_sync(0xffffffffu, sum, o);
        sc[lane] = ex / sum;
    }
    __syncthreads();
    {
        float acc = 0.f, msum = 0.f;
        #pragma unroll 4
        for (int q = 0; q < Qq; ++q) { float v = qe[q * Dd + t]; acc += sc[q] * v; msum += v; }
        qemb[t] = acc;
        marr[t] = msum * (1.f / (float)Qq);
    }
    __syncthreads();
    {
        float acc = bqc[t];
        for (int d = 0; d < Dd; ++d) acc += marr[d] * Wqc[d * Dd + t];
        qproj[t] = acc;
    }
}

// ---------------- gate ----------------
__global__ void gate_kernel(const float* __restrict__ x_in, const float* __restrict__ tmat,
                            const float* __restrict__ bc, const float* __restrict__ qemb,
                            float* __restrict__ xout)
{
    __shared__ float sbuf[8];
    const int n = blockIdx.x, t = threadIdx.x;   // 256
    const float* trow = tmat + (long)n * Dd;
    float s = 0.f;
    for (int d = t; d < Dd; d += 256) s += (trow[d] + bc[d]) * qemb[d];
    s = block_sum256(s, sbuf);
    float p = 1.f / (1.f + __expf(-s));
    const float* xrow = x_in + (long)n * Dd;
    float* orow = xout + (long)n * Dd;
    for (int d = t; d < Dd; d += 256) orow[d] = p * xrow[d] + (1.f - p) * qemb[d];
}

// ---------------- f1/f2 = Wh · a1/a2 ----------------
__global__ void f12_kernel(const float* __restrict__ Wh, const float* __restrict__ a1,
                           const float* __restrict__ a2, float* __restrict__ f1,
                           float* __restrict__ f2)
{
    __shared__ float sbuf[8];
    const int rn = blockIdx.x;
    const int r  = rn >> 11;
    const float* row = Wh + (long)rn * Dd;
    const float* p1 = a1 + r * Dd;
    const float* p2 = a2 + r * Dd;
    float s1 = 0.f, s2 = 0.f;
    for (int d = threadIdx.x; d < Dd; d += 256) {
        float v = row[d];
        s1 += v * p1[d];
        s2 += v * p2[d];
    }
    s1 = block_sum256(s1, sbuf);
    s2 = block_sum256(s2, sbuf);
    if (threadIdx.x == 0) { f1[rn] = s1; f2[rn] = s2; }
}

// ---------------- masked softmax row (unnormalized exp + invsum) ----------------
__global__ void att_kernel(const float* __restrict__ f1, const float* __restrict__ f2,
                           const unsigned* __restrict__ mask, float* __restrict__ att,
                           float* __restrict__ invs)
{
    __shared__ float sbuf[8];
    const int rn = blockIdx.x;
    const int r  = rn >> 11;
    const unsigned* mrow = mask + (long)rn * (Nn / 32);
    float* orow = att + (long)rn * Nn;
    const float f1v = f1[rn];
    const float* f2r = f2 + r * Nn;
    const int t = threadIdx.x;   // 256, 8 elems each

    float e[8];
    float mx = -INFINITY;
    #pragma unroll
    for (int i = 0; i < 8; ++i) {
        int m = t + i * 256;
        float v = f1v + f2r[m];
        v = v > 0.f ? v : ALPHA * v;
        unsigned bit = (mrow[m >> 5] >> (m & 31)) & 1u;
        e[i] = bit ? v : -1e30f;
        mx = fmaxf(mx, e[i]);
    }
    mx = block_max256(mx, sbuf);

    float sum = 0.f;
    float ex[8];
    #pragma unroll
    for (int i = 0; i < 8; ++i) {
        ex[i] = __expf(e[i] - mx);
        sum += ex[i];
    }
    sum = block_sum256(sum, sbuf);
    #pragma unroll
    for (int i = 0; i < 8; ++i) orow[t + i * 256] = ex[i];
    if (t == 0) invs[rn] = 1.f / sum;
}

// ---------------- scale + elu (+ optional LayerNorm) + max over relations ----------------
__global__ void postproc_kernel(const float* __restrict__ go, float* __restrict__ xout,
                                const float* __restrict__ g, const float* __restrict__ b,
                                const float* __restrict__ invs, int do_ln)
{
    __shared__ float sbuf[8];
    const int n = blockIdx.x, t = threadIdx.x;   // 256 threads, 2 feats each
    float m0 = -INFINITY, m1 = -INFINITY;
    for (int r = 0; r < Rr; ++r) {
        const float inv = invs[r * Nn + n];
        const float* row = go + (long)(r * Nn + n) * Dd;
        float v0 = row[t] * inv, v1 = row[t + 256] * inv;
        v0 = v0 > 0.f ? v0 : __expf(v0) - 1.f;
        v1 = v1 > 0.f ? v1 : __expf(v1) - 1.f;
        if (do_ln) {
            float s = block_sum256(v0 + v1, sbuf);
            float mu = s * (1.f / (float)Dd);
            float d0 = v0 - mu, d1 = v1 - mu;
            float q = block_sum256(d0 * d0 + d1 * d1, sbuf);
            float ivn = rsqrtf(q * (1.f / (float)Dd) + EPSLN);
            v0 = d0 * ivn * g[t] + b[t];
            v1 = d1 * ivn * g[t + 256] + b[t + 256];
        }
        m0 = fmaxf(m0, v0);
        m1 = fmaxf(m1, v1);
    }
    xout[(long)n * Dd + t] = m0;
    xout[(long)n * Dd + t + 256] = m1;
}

__global__ void copy_kernel(float* __restrict__ dst, const float* __restrict__ src)
{
    int i = blockIdx.x * 256 + threadIdx.x;
    dst[i] = src[i];
}

// ---------------- choice layer ----------------
__global__ void choice_kernel(const float* __restrict__ xenc, const int* __restrict__ cidx,
                              const float* __restrict__ qproj, const float* __restrict__ Wout,
                              const float* __restrict__ bout, float* __restrict__ out)
{
    __shared__ float sc[5][Cc];
    __shared__ float dw[5][Cc];
    __shared__ float lg[5];
    const int t = threadIdx.x;       // 512
    const int w = t >> 5, lane = t & 31;

    for (int p = w; p < 5 * Cc; p += 16) {
        int node = cidx[p];
        const float* row = xenc + (long)node * Dd;
        float s1 = 0.f, s2 = 0.f;
        for (int d = lane; d < Dd; d += 32) {
            float v = row[d];
            s1 += v * qproj[d];
            s2 += v * Wout[d];
        }
        #pragma unroll
        for (int o = 16; o > 0; o >>= 1) {
            s1 += __shfl_xor_sync(0xffffffffu, s1, o);
            s2 += __shfl_xor_sync(0xffffffffu, s2, o);
        }
        if (lane == 0) { sc[p / Cc][p % Cc] = s1; dw[p / Cc][p % Cc] = s2; }
    }
    __syncthreads();
    if (w < 5) {
        float v0 = sc[w][lane], v1 = sc[w][lane + 32];
        float mx = fmaxf(v0, v1);
        #pragma unroll
        for (int o = 16; o > 0; o >>= 1) mx = fmaxf(mx, __shfl_xor_sync(0xffffffffu, mx, o));
        float e0 = __expf(v0 - mx), e1 = __expf(v1 - mx);
        float s = e0 + e1;
        float l = e0 * dw[w][lane] + e1 * dw[w][lane + 32];
        #pragma unroll
        for (int o = 16; o > 0; o >>= 1) {
            s += __shfl_xor_sync(0xffffffffu, s, o);
            l += __shfl_xor_sync(0xffffffffu, l, o);
        }
        if (lane == 0) lg[w] = l / s + bout[0];
    }
    __syncthreads();
    if (t == 0) {
        float mx = lg[0];
        #pragma unroll
        for (int k = 1; k < 5; ++k) mx = fmaxf(mx, lg[k]);
        float sum = 0.f;
        #pragma unroll
        for (int k = 0; k < 5; ++k) sum += __expf(lg[k] - mx);
        float lse = mx + logf(sum);
        #pragma unroll
        for (int k = 0; k < 5; ++k) out[k] = lg[k] - lse;
    }
}

// ---------------- launcher ----------------
extern "C" void kernel_launch(void* const* d_in, const int* in_sizes, int n_in,
                              void* d_out, int out_size)
{
    const float* x    = (const float*)d_in[0];
    const int*   adj  = (const int*)  d_in[1];
    const float* qe   = (const float*)d_in[2];
    const int*   cidx = (const int*)  d_in[4];
    const float* Wc   = (const float*)d_in[5];
    const float* bc   = (const float*)d_in[6];
    const float* wq   = (const float*)d_in[7];
    const float* encW = (const float*)d_in[8];
    const float* ea1  = (const float*)d_in[9];
    const float* ea2  = (const float*)d_in[10];
    const float* decW = (const float*)d_in[11];
    const float* da1  = (const float*)d_in[12];
    const float* da2  = (const float*)d_in[13];
    const float* lng  = (const float*)d_in[14];
    const float* lnb  = (const float*)d_in[15];
    const float* Wqc  = (const float*)d_in[16];
    const float* bqc  = (const float*)d_in[17];
    const float* Wout = (const float*)d_in[18];
    const float* bout = (const float*)d_in[19];
    float* out = (float*)d_out;

    float *px, *pxenc, *pt, *pWh, *patt, *pgo, *pf1, *pf2, *pinv, *pqemb, *pqproj;
    unsigned* pmask;
    cudaGetSymbolAddress((void**)&px,     g_x);
    cudaGetSymbolAddress((void**)&pxenc,  g_xenc);
    cudaGetSymbolAddress((void**)&pt,     g_t);
    cudaGetSymbolAddress((void**)&pWh,    g_Wh);
    cudaGetSymbolAddress((void**)&patt,   g_att);
    cudaGetSymbolAddress((void**)&pgo,    g_go);
    cudaGetSymbolAddress((void**)&pf1,    g_f1);
    cudaGetSymbolAddress((void**)&pf2,    g_f2);
    cudaGetSymbolAddress((void**)&pinv,   g_inv);
    cudaGetSymbolAddress((void**)&pmask,  g_mask);
    cudaGetSymbolAddress((void**)&pqemb,  g_qemb);
    cudaGetSymbolAddress((void**)&pqproj, g_qproj);

    // 0) pack adjacency to bitmask (reused by all 4 layers)
    pack_adj_kernel<<<Rr * Nn, 256>>>(adj, pmask);

    // 1) question layer
    question_kernel<<<1, 512>>>(qe, wq, Wqc, bqc, pqemb, pqproj);

    // 2) gate: t = x @ Wc^T (NT), then elementwise gate
    mma_gemm<1><<<dim3(Dd / 128, Nn / 128, 1), 256>>>(x, Wc, pt, Nn, Dd, Dd, 0, 0, 0);
    gate_kernel<<<Nn, 256>>>(x, pt, bc, pqemb, px);

    // 3) encoder: 2 heads, LN + max
    for (int h = 0; h < 2; ++h) {
        mma_gemm<0><<<dim3(Dd / 128, Nn / 128, Rr), 256>>>(
            px, encW + (long)h * Rr * Dd * Dd, pWh, Nn, Dd, Dd,
            0, (long)Dd * Dd, (long)Nn * Dd);
        f12_kernel<<<Rr * Nn, 256>>>(pWh, ea1 + h * Rr * Dd, ea2 + h * Rr * Dd, pf1, pf2);
        att_kernel<<<Rr * Nn, 256>>>(pf1, pf2, pmask, patt, pinv);
        mma_gemm<0><<<dim3(Dd / 128, Nn / 128, Rr), 256>>>(
            patt, pWh, pgo, Nn, Dd, Nn,
            (long)Nn * Nn, (long)Nn * Dd, (long)Nn * Dd);
        postproc_kernel<<<Nn, 256>>>(pgo, px, lng, lnb, pinv, 1);
    }
    copy_kernel<<<Nn * Dd / 256, 256>>>(pxenc, px);

    // 4) decoder: 2 heads, LN only on first, write final xd straight to output
    float* xdout = (out_size >= 5 + Nn * Dd) ? (out + 5) : px;
    for (int i = 0; i < 2; ++i) {
        mma_gemm<0><<<dim3(Dd / 128, Nn / 128, Rr), 256>>>(
            px, decW + (long)i * Rr * Dd * Dd, pWh, Nn, Dd, Dd,
            0, (long)Dd * Dd, (long)Nn * Dd);
        f12_kernel<<<Rr * Nn, 256>>>(pWh, da1 + i * Rr * Dd, da2 + i * Rr * Dd, pf1, pf2);
        att_kernel<<<Rr * Nn, 256>>>(pf1, pf2, pmask, patt, pinv);
        mma_gemm<0><<<dim3(Dd / 128, Nn / 128, Rr), 256>>>(
            patt, pWh, pgo, Nn, Dd, Nn,
            (long)Nn * Nn, (long)Nn * Dd, (long)Nn * Dd);
        postproc_kernel<<<Nn, 256>>>(pgo, (i == 1) ? xdout : px, lng, lnb, pinv, (i == 0) ? 1 : 0);
    }

    // 5) choice layer -> out[0..4]
    choice_kernel<<<1, 512>>>(pxenc, cidx, pqproj, Wout, bout, out);
}

// round 11
// speedup vs baseline: 1.6126x; 1.0379x over previous
#include <cuda_runtime.h>
#include <cuda_fp16.h>
#include <cuda_bf16.h>
#include <math.h>

#define Nn 2048
#define Dd 512
#define Rr 4
#define Qq 32
#define Cc 64
#define ALPHA 0.2f
#define EPSLN 1e-5f

// ---------------- scratch (device globals; allocation-free) ----------------
__device__ __half g_xh[Nn * Dd];              // layer activations (f16)
__device__ float  g_xenc[Nn * Dd];            // encoder output fp32 (choice layer)
__device__ float  g_t[Nn * Dd];               // gate GEMM temp (fp32)
__device__ __half g_Whh[Rr * Nn * Dd];        // projected features (f16)
__device__ float  g_go[Rr * Nn * Dd];         // att @ Wh (fp32)
__device__ __half g_atth[Rr * Nn * Nn];       // unnormalized exp values (f16, 32MB)
__device__ __half g_w16[4 * Rr * Dd * Dd];    // enc+dec weights converted to f16
__device__ float  g_f1[Rr * Nn];
__device__ float  g_f2[Rr * Nn];
__device__ float  g_inv[Rr * Nn];             // 1/rowsum (deferred softmax norm)
__device__ unsigned g_mask[Rr * Nn * (Nn / 32)];  // adj>0 bitmask (2MB)
__device__ float  g_qemb[Dd];
__device__ float  g_qproj[Dd];

// ---------------- helpers ----------------
__device__ __forceinline__ unsigned pack_h2(float x, float y) {
    __half2 h = __floats2half2_rn(x, y);
    return *reinterpret_cast<unsigned*>(&h);
}

__device__ __forceinline__ void mma_f16(float c[4], const unsigned a[4], const unsigned b[2]) {
    asm volatile(
        "mma.sync.aligned.m16n8k16.row.col.f32.f16.f16.f32 "
        "{%0,%1,%2,%3}, {%4,%5,%6,%7}, {%8,%9}, {%0,%1,%2,%3};"
        : "+f"(c[0]), "+f"(c[1]), "+f"(c[2]), "+f"(c[3])
        : "r"(a[0]), "r"(a[1]), "r"(a[2]), "r"(a[3]), "r"(b[0]), "r"(b[1]));
}

__device__ __forceinline__ float block_sum256(float v, float* sbuf) {
    __syncthreads();
    #pragma unroll
    for (int o = 16; o > 0; o >>= 1) v += __shfl_xor_sync(0xffffffffu, v, o);
    if ((threadIdx.x & 31) == 0) sbuf[threadIdx.x >> 5] = v;
    __syncthreads();
    float tot = 0.f;
    #pragma unroll
    for (int i = 0; i < 8; ++i) tot += sbuf[i];
    return tot;
}

__device__ __forceinline__ float block_max256(float v, float* sbuf) {
    __syncthreads();
    #pragma unroll
    for (int o = 16; o > 0; o >>= 1) v = fmaxf(v, __shfl_xor_sync(0xffffffffu, v, o));
    if ((threadIdx.x & 31) == 0) sbuf[threadIdx.x >> 5] = v;
    __syncthreads();
    float tot = -INFINITY;
    #pragma unroll
    for (int i = 0; i < 8; ++i) tot = fmaxf(tot, sbuf[i]);
    return tot;
}

// ---------------- fp32->f16 weight conversion ----------------
__global__ void convert_kernel(__half* __restrict__ dst, const float* __restrict__ src)
{
    int i = blockIdx.x * 256 + threadIdx.x;
    dst[i] = __float2half_rn(src[i]);
}

// ---------------- f16-input tensor-core GEMM (v4) ----------------
// 128x128x16 CTA tile, 8 warps (32x64 warp tile), single-stage, m16n8k16.
// A [M,K] f16 row-major, B [K,N] f16 row-major. OUTH: C f16 else fp32.
// smem: half2-packed (k,k+1) pairs, stride 136 -> fragment loads conflict-free.
template <int OUTH>
__global__ void __launch_bounds__(256, 2) mma_gemm_h(
    const __half* __restrict__ A, const __half* __restrict__ B, void* Cv,
    int M, int N, int K, long sA, long sB, long sC)
{
    A += (long)blockIdx.z * sA;
    B += (long)blockIdx.z * sB;
    const long cofs = (long)blockIdx.z * sC;

    __shared__ unsigned As[8][136];
    __shared__ unsigned Bs[8][136];

    const int t = threadIdx.x, lane = t & 31, wid = t >> 5;
    const int bm = blockIdx.y * 128, bn = blockIdx.x * 128;
    const int wm = (wid & 3) * 32, wn = (wid >> 2) * 64;
    const int kl = lane & 3, gm = lane >> 2;

    float acc[2][8][4];
    #pragma unroll
    for (int mi = 0; mi < 2; ++mi)
        #pragma unroll
        for (int ni = 0; ni < 8; ++ni)
            #pragma unroll
            for (int c = 0; c < 4; ++c) acc[mi][ni][c] = 0.f;

    // A staging: 128 rows x 16 halves, one uint4 per thread (conflict-free STS)
    const int rowA = t & 127;
    const int koff = (t >> 7) * 8;     // 0 or 8
    const int sA0  = koff >> 1;        // slot base 0 or 4
    // B staging: kpB row-pair, 4 n-columns per thread
    const int kpB = t >> 5;            // 0..7
    const int nqB = (t & 31) * 4;

    uint4 ua;
    uint2 ub0, ub1;
    ua  = *(const uint4*)(A + (long)(bm + rowA) * K + koff);
    ub0 = *(const uint2*)(B + (long)(2 * kpB) * N + bn + nqB);
    ub1 = *(const uint2*)(B + (long)(2 * kpB + 1) * N + bn + nqB);

    for (int k0 = 0; k0 < K; k0 += 16) {
        // stage current tile (no conversion — already f16)
        As[sA0 + 0][rowA] = ua.x;
        As[sA0 + 1][rowA] = ua.y;
        As[sA0 + 2][rowA] = ua.z;
        As[sA0 + 3][rowA] = ua.w;
        {
            uint4 bp;
            bp.x = __byte_perm(ub0.x, ub1.x, 0x5410);
            bp.y = __byte_perm(ub0.x, ub1.x, 0x7632);
            bp.z = __byte_perm(ub0.y, ub1.y, 0x5410);
            bp.w = __byte_perm(ub0.y, ub1.y, 0x7632);
            *(uint4*)&Bs[kpB][nqB] = bp;
        }
        __syncthreads();

        if (k0 + 16 < K) {
            int kn = k0 + 16;
            ua  = *(const uint4*)(A + (long)(bm + rowA) * K + kn + koff);
            ub0 = *(const uint2*)(B + (long)(kn + 2 * kpB) * N + bn + nqB);
            ub1 = *(const uint2*)(B + (long)(kn + 2 * kpB + 1) * N + bn + nqB);
        }

        // compute: one m16n8k16 per (mi, ni)
        {
            unsigned a[2][4], bv[8][2];
            #pragma unroll
            for (int mi = 0; mi < 2; ++mi) {
                int m = wm + mi * 16 + gm;
                a[mi][0] = As[kl][m];
                a[mi][1] = As[kl][m + 8];
                a[mi][2] = As[kl + 4][m];
                a[mi][3] = As[kl + 4][m + 8];
            }
            #pragma unroll
            for (int ni = 0; ni < 8; ++ni) {
                int n = wn + ni * 8 + gm;
                bv[ni][0] = Bs[kl][n];
                bv[ni][1] = Bs[kl + 4][n];
            }
            #pragma unroll
            for (int mi = 0; mi < 2; ++mi)
                #pragma unroll
                for (int ni = 0; ni < 8; ++ni)
                    mma_f16(acc[mi][ni], a[mi], bv[ni]);
        }
        __syncthreads();
    }

    // epilogue
    if (OUTH) {
        unsigned* Cw = (unsigned*)((__half*)Cv + cofs);
        #pragma unroll
        for (int mi = 0; mi < 2; ++mi) {
            int row0 = bm + wm + mi * 16 + gm;
            #pragma unroll
            for (int ni = 0; ni < 8; ++ni) {
                int col = bn + wn + ni * 8 + kl * 2;
                Cw[((long)row0 * N + col) >> 1]       = pack_h2(acc[mi][ni][0], acc[mi][ni][1]);
                Cw[((long)(row0 + 8) * N + col) >> 1] = pack_h2(acc[mi][ni][2], acc[mi][ni][3]);
            }
        }
    } else {
        float* Cf = (float*)Cv + cofs;
        #pragma unroll
        for (int mi = 0; mi < 2; ++mi) {
            int row0 = bm + wm + mi * 16 + gm;
            #pragma unroll
            for (int ni = 0; ni < 8; ++ni) {
                int col = bn + wn + ni * 8 + kl * 2;
                *(float2*)(Cf + (long)row0 * N + col) = make_float2(acc[mi][ni][0], acc[mi][ni][1]);
                *(float2*)(Cf + (long)(row0 + 8) * N + col) = make_float2(acc[mi][ni][2], acc[mi][ni][3]);
            }
        }
    }
}

// ---------------- fp32-input f16 GEMM (gate only, TRANSB) ----------------
__global__ void __launch_bounds__(256, 2) mma_gemm_nt(
    const float* __restrict__ A, const float* __restrict__ B, float* __restrict__ C,
    int M, int N, int K)
{
    __shared__ unsigned As[8][136];
    __shared__ unsigned Bs[8][136];

    const int t = threadIdx.x, lane = t & 31, wid = t >> 5;
    const int bm = blockIdx.y * 128, bn = blockIdx.x * 128;
    const int wm = (wid & 3) * 32, wn = (wid >> 2) * 64;
    const int kl = lane & 3, gm = lane >> 2;

    float acc[2][8][4];
    #pragma unroll
    for (int mi = 0; mi < 2; ++mi)
        #pragma unroll
        for (int ni = 0; ni < 8; ++ni)
            #pragma unroll
            for (int c = 0; c < 4; ++c) acc[mi][ni][c] = 0.f;

    const int rowA0 = t >> 2;
    const int kqA  = (t & 3) * 4;
    const int sA0  = kqA >> 1;

    float4 fa0, fa1, fb0, fb1;
    fa0 = *(const float4*)(A + (long)(bm + rowA0) * K + kqA);
    fa1 = *(const float4*)(A + (long)(bm + rowA0 + 64) * K + kqA);
    fb0 = *(const float4*)(B + (long)(bn + rowA0) * K + kqA);
    fb1 = *(const float4*)(B + (long)(bn + rowA0 + 64) * K + kqA);

    for (int k0 = 0; k0 < K; k0 += 16) {
        As[sA0 + 0][rowA0]      = pack_h2(fa0.x, fa0.y);
        As[sA0 + 1][rowA0]      = pack_h2(fa0.z, fa0.w);
        As[sA0 + 0][rowA0 + 64] = pack_h2(fa1.x, fa1.y);
        As[sA0 + 1][rowA0 + 64] = pack_h2(fa1.z, fa1.w);
        Bs[sA0 + 0][rowA0]      = pack_h2(fb0.x, fb0.y);
        Bs[sA0 + 1][rowA0]      = pack_h2(fb0.z, fb0.w);
        Bs[sA0 + 0][rowA0 + 64] = pack_h2(fb1.x, fb1.y);
        Bs[sA0 + 1][rowA0 + 64] = pack_h2(fb1.z, fb1.w);
        __syncthreads();

        if (k0 + 16 < K) {
            int kn = k0 + 16;
            fa0 = *(const float4*)(A + (long)(bm + rowA0) * K + kn + kqA);
            fa1 = *(const float4*)(A + (long)(bm + rowA0 + 64) * K + kn + kqA);
            fb0 = *(const float4*)(B + (long)(bn + rowA0) * K + kn + kqA);
            fb1 = *(const float4*)(B + (long)(bn + rowA0 + 64) * K + kn + kqA);
        }

        {
            unsigned a[2][4], bv[8][2];
            #pragma unroll
            for (int mi = 0; mi < 2; ++mi) {
                int m = wm + mi * 16 + gm;
                a[mi][0] = As[kl][m];
                a[mi][1] = As[kl][m + 8];
                a[mi][2] = As[kl + 4][m];
                a[mi][3] = As[kl + 4][m + 8];
            }
            #pragma unroll
            for (int ni = 0; ni < 8; ++ni) {
                int n = wn + ni * 8 + gm;
                bv[ni][0] = Bs[kl][n];
                bv[ni][1] = Bs[kl + 4][n];
            }
            #pragma unroll
            for (int mi = 0; mi < 2; ++mi)
                #pragma unroll
                for (int ni = 0; ni < 8; ++ni)
                    mma_f16(acc[mi][ni], a[mi], bv[ni]);
        }
        __syncthreads();
    }

    #pragma unroll
    for (int mi = 0; mi < 2; ++mi) {
        int row0 = bm + wm + mi * 16 + gm;
        #pragma unroll
        for (int ni = 0; ni < 8; ++ni) {
            int col = bn + wn + ni * 8 + kl * 2;
            *(float2*)(C + (long)row0 * N + col) = make_float2(acc[mi][ni][0], acc[mi][ni][1]);
            *(float2*)(C + (long)(row0 + 8) * N + col) = make_float2(acc[mi][ni][2], acc[mi][ni][3]);
        }
    }
}

// ---------------- pack adj -> bitmask ----------------
__global__ void pack_adj_kernel(const int* __restrict__ adj, unsigned* __restrict__ mask)
{
    const int row = blockIdx.x;
    const int lane = threadIdx.x & 31, w = threadIdx.x >> 5;
    const int* arow = adj + (long)row * Nn;
    for (int wi = w; wi < Nn / 32; wi += 8) {
        unsigned b = __ballot_sync(0xffffffffu, arow[wi * 32 + lane] > 0);
        if (lane == 0) mask[(long)row * (Nn / 32) + wi] = b;
    }
}

// ---------------- question layer ----------------
__global__ void question_kernel(const float* __restrict__ qe, const float* __restrict__ wq,
                                const float* __restrict__ Wqc, const float* __restrict__ bqc,
                                float* __restrict__ qemb, float* __restrict__ qproj)
{
    __shared__ float logits[Qq];
    __shared__ float sc[Qq];
    __shared__ float marr[Dd];
    const int t = threadIdx.x;          // 512
    const int w = t >> 5, lane = t & 31;

    for (int q = w; q < Qq; q += 16) {
        float s = 0.f;
        for (int d = lane; d < Dd; d += 32) s += qe[q * Dd + d] * wq[d];
        #pragma unroll
        for (int o = 16; o > 0; o >>= 1) s += __shfl_xor_sync(0xffffffffu, s, o);
        if (lane == 0) logits[q] = s;
    }
    __syncthreads();
    if (w == 0) {
        float v = logits[lane];
        float mx = v;
        #pragma unroll
        for (int o = 16; o > 0; o >>= 1) mx = fmaxf(mx, __shfl_xor_sync(0xffffffffu, mx, o));
        float ex = __expf(v - mx);
        float sum = ex;
        #pragma unroll
        for (int o = 16; o > 0; o >>= 1) sum += __shfl_xor_sync(0xffffffffu, sum, o);
        sc[lane] = ex / sum;
    }
    __syncthreads();
    {
        float acc = 0.f, msum = 0.f;
        #pragma unroll 4
        for (int q = 0; q < Qq; ++q) { float v = qe[q * Dd + t]; acc += sc[q] * v; msum += v; }
        qemb[t] = acc;
        marr[t] = msum * (1.f / (float)Qq);
    }
    __syncthreads();
    {
        float acc = bqc[t];
        for (int d = 0; d < Dd; ++d) acc += marr[d] * Wqc[d * Dd + t];
        qproj[t] = acc;
    }
}

// ---------------- gate: writes f16 activations ----------------
__global__ void gate_kernel(const float* __restrict__ x_in, const float* __restrict__ tmat,
                            const float* __restrict__ bc, const float* __restrict__ qemb,
                            unsigned* __restrict__ xh)
{
    __shared__ float sbuf[8];
    const int n = blockIdx.x, t = threadIdx.x;   // 256
    const float* trow = tmat + (long)n * Dd;
    float s = 0.f;
    for (int d = t; d < Dd; d += 256) s += (trow[d] + bc[d]) * qemb[d];
    s = block_sum256(s, sbuf);
    float p = 1.f / (1.f + __expf(-s));
    float2 xv = *(const float2*)(x_in + (long)n * Dd + 2 * t);
    float q0 = qemb[2 * t], q1 = qemb[2 * t + 1];
    xh[(long)n * 256 + t] = pack_h2(p * xv.x + (1.f - p) * q0, p * xv.y + (1.f - p) * q1);
}

// ---------------- f1/f2 = Wh · a1/a2 (Wh f16) ----------------
__global__ void f12_kernel(const __half* __restrict__ Whh, const float* __restrict__ a1,
                           const float* __restrict__ a2, float* __restrict__ f1,
                           float* __restrict__ f2)
{
    __shared__ float sbuf[8];
    const int rn = blockIdx.x;
    const int r  = rn >> 11;
    const __half2* row = (const __half2*)(Whh + (long)rn * Dd);
    const float* p1 = a1 + r * Dd;
    const float* p2 = a2 + r * Dd;
    const int t = threadIdx.x;    // 256
    float2 v = __half22float2(row[t]);
    float s1 = v.x * p1[2 * t] + v.y * p1[2 * t + 1];
    float s2 = v.x * p2[2 * t] + v.y * p2[2 * t + 1];
    s1 = block_sum256(s1, sbuf);
    s2 = block_sum256(s2, sbuf);
    if (t == 0) { f1[rn] = s1; f2[rn] = s2; }
}

// ---------------- masked softmax row -> f16 unnormalized exp + invsum ----------------
__global__ void att_kernel(const float* __restrict__ f1, const float* __restrict__ f2,
                           const unsigned* __restrict__ mask, __half* __restrict__ att,
                           float* __restrict__ invs)
{
    __shared__ float sbuf[8];
    const int rn = blockIdx.x;
    const int r  = rn >> 11;
    const unsigned* mrow = mask + (long)rn * (Nn / 32);
    const float f1v = f1[rn];
    const float* f2r = f2 + r * Nn;
    const int t = threadIdx.x;   // 256, 8 consecutive elems each
    const int m0 = t * 8;

    float4 fa = *(const float4*)(f2r + m0);
    float4 fb = *(const float4*)(f2r + m0 + 4);
    unsigned mw = mrow[m0 >> 5] >> (m0 & 31);

    float e[8];
    e[0] = fa.x; e[1] = fa.y; e[2] = fa.z; e[3] = fa.w;
    e[4] = fb.x; e[5] = fb.y; e[6] = fb.z; e[7] = fb.w;
    float mx = -INFINITY;
    #pragma unroll
    for (int i = 0; i < 8; ++i) {
        float v = f1v + e[i];
        v = v > 0.f ? v : ALPHA * v;
        e[i] = ((mw >> i) & 1u) ? v : -1e30f;
        mx = fmaxf(mx, e[i]);
    }
    mx = block_max256(mx, sbuf);

    float sum = 0.f;
    float ex[8];
    #pragma unroll
    for (int i = 0; i < 8; ++i) {
        ex[i] = __expf(e[i] - mx);
        sum += ex[i];
    }
    sum = block_sum256(sum, sbuf);

    uint4 o;
    o.x = pack_h2(ex[0], ex[1]);
    o.y = pack_h2(ex[2], ex[3]);
    o.z = pack_h2(ex[4], ex[5]);
    o.w = pack_h2(ex[6], ex[7]);
    *(uint4*)(att + (long)rn * Nn + m0) = o;
    if (t == 0) invs[rn] = 1.f / sum;
}

// ---------------- scale + elu (+ LN) + max over relations; dual-format out ----------------
// out_f written with SCALAR stores (may be 4-byte aligned only, e.g. out+5).
__global__ void postproc_kernel(const float* __restrict__ go, unsigned* __restrict__ out_h,
                                float* __restrict__ out_f,
                                const float* __restrict__ g, const float* __restrict__ b,
                                const float* __restrict__ invs, int do_ln)
{
    __shared__ float sbuf[8];
    const int n = blockIdx.x, t = threadIdx.x;   // 256 threads, pair (2t, 2t+1)
    float m0 = -INFINITY, m1 = -INFINITY;
    for (int r = 0; r < Rr; ++r) {
        const float inv = invs[r * Nn + n];
        float2 rv = *(const float2*)(go + (long)(r * Nn + n) * Dd + 2 * t);
        float v0 = rv.x * inv, v1 = rv.y * inv;
        v0 = v0 > 0.f ? v0 : __expf(v0) - 1.f;
        v1 = v1 > 0.f ? v1 : __expf(v1) - 1.f;
        if (do_ln) {
            float s = block_sum256(v0 + v1, sbuf);
            float mu = s * (1.f / (float)Dd);
            float d0 = v0 - mu, d1 = v1 - mu;
            float q = block_sum256(d0 * d0 + d1 * d1, sbuf);
            float ivn = rsqrtf(q * (1.f / (float)Dd) + EPSLN);
            v0 = d0 * ivn * g[2 * t] + b[2 * t];
            v1 = d1 * ivn * g[2 * t + 1] + b[2 * t + 1];
        }
        m0 = fmaxf(m0, v0);
        m1 = fmaxf(m1, v1);
    }
    if (out_h) out_h[(long)n * 256 + t] = pack_h2(m0, m1);
    if (out_f) {
        out_f[(long)n * Dd + 2 * t]     = m0;   // scalar stores: alignment-safe
        out_f[(long)n * Dd + 2 * t + 1] = m1;
    }
}

// ---------------- choice layer ----------------
__global__ void choice_kernel(const float* __restrict__ xenc, const int* __restrict__ cidx,
                              const float* __restrict__ qproj, const float* __restrict__ Wout,
                              const float* __restrict__ bout, float* __restrict__ out)
{
    __shared__ float sc[5][Cc];
    __shared__ float dw[5][Cc];
    __shared__ float lg[5];
    const int t = threadIdx.x;       // 512
    const int w = t >> 5, lane = t & 31;

    for (int p = w; p < 5 * Cc; p += 16) {
        int node = cidx[p];
        const float* row = xenc + (long)node * Dd;
        float s1 = 0.f, s2 = 0.f;
        for (int d = lane; d < Dd; d += 32) {
            float v = row[d];
            s1 += v * qproj[d];
            s2 += v * Wout[d];
        }
        #pragma unroll
        for (int o = 16; o > 0; o >>= 1) {
            s1 += __shfl_xor_sync(0xffffffffu, s1, o);
            s2 += __shfl_xor_sync(0xffffffffu, s2, o);
        }
        if (lane == 0) { sc[p / Cc][p % Cc] = s1; dw[p / Cc][p % Cc] = s2; }
    }
    __syncthreads();
    if (w < 5) {
        float v0 = sc[w][lane], v1 = sc[w][lane + 32];
        float mx = fmaxf(v0, v1);
        #pragma unroll
        for (int o = 16; o > 0; o >>= 1) mx = fmaxf(mx, __shfl_xor_sync(0xffffffffu, mx, o));
        float e0 = __expf(v0 - mx), e1 = __expf(v1 - mx);
        float s = e0 + e1;
        float l = e0 * dw[w][lane] + e1 * dw[w][lane + 32];
        #pragma unroll
        for (int o = 16; o > 0; o >>= 1) {
            s += __shfl_xor_sync(0xffffffffu, s, o);
            l += __shfl_xor_sync(0xffffffffu, l, o);
        }
        if (lane == 0) lg[w] = l / s + bout[0];
    }
    __syncthreads();
    if (t == 0) {
        float mx = lg[0];
        #pragma unroll
        for (int k = 1; k < 5; ++k) mx = fmaxf(mx, lg[k]);
        float sum = 0.f;
        #pragma unroll
        for (int k = 0; k < 5; ++k) sum += __expf(lg[k] - mx);
        float lse = mx + logf(sum);
        #pragma unroll
        for (int k = 0; k < 5; ++k) out[k] = lg[k] - lse;
    }
}

// ---------------- launcher ----------------
extern "C" void kernel_launch(void* const* d_in, const int* in_sizes, int n_in,
                              void* d_out, int out_size)
{
    const float* x    = (const float*)d_in[0];
    const int*   adj  = (const int*)  d_in[1];
    const float* qe   = (const float*)d_in[2];
    const int*   cidx = (const int*)  d_in[4];
    const float* Wc   = (const float*)d_in[5];
    const float* bc   = (const float*)d_in[6];
    const float* wq   = (const float*)d_in[7];
    const float* encW = (const float*)d_in[8];
    const float* ea1  = (const float*)d_in[9];
    const float* ea2  = (const float*)d_in[10];
    const float* decW = (const float*)d_in[11];
    const float* da1  = (const float*)d_in[12];
    const float* da2  = (const float*)d_in[13];
    const float* lng  = (const float*)d_in[14];
    const float* lnb  = (const float*)d_in[15];
    const float* Wqc  = (const float*)d_in[16];
    const float* bqc  = (const float*)d_in[17];
    const float* Wout = (const float*)d_in[18];
    const float* bout = (const float*)d_in[19];
    float* out = (float*)d_out;

    __half *pxh, *pWhh, *patth, *pw16;
    float *pxenc, *pt, *pgo, *pf1, *pf2, *pinv, *pqemb, *pqproj;
    unsigned* pmask;
    cudaGetSymbolAddress((void**)&pxh,    g_xh);
    cudaGetSymbolAddress((void**)&pxenc,  g_xenc);
    cudaGetSymbolAddress((void**)&pt,     g_t);
    cudaGetSymbolAddress((void**)&pWhh,   g_Whh);
    cudaGetSymbolAddress((void**)&patth,  g_atth);
    cudaGetSymbolAddress((void**)&pgo,    g_go);
    cudaGetSymbolAddress((void**)&pw16,   g_w16);
    cudaGetSymbolAddress((void**)&pf1,    g_f1);
    cudaGetSymbolAddress((void**)&pf2,    g_f2);
    cudaGetSymbolAddress((void**)&pinv,   g_inv);
    cudaGetSymbolAddress((void**)&pmask,  g_mask);
    cudaGetSymbolAddress((void**)&pqemb,  g_qemb);
    cudaGetSymbolAddress((void**)&pqproj, g_qproj);

    const long WSZ = (long)2 * Rr * Dd * Dd;   // elements per (enc|dec) weight set

    // 0) one-time conversions + adjacency bitmask
    convert_kernel<<<(int)(WSZ / 256), 256>>>(pw16, encW);
    convert_kernel<<<(int)(WSZ / 256), 256>>>(pw16 + WSZ, decW);
    pack_adj_kernel<<<Rr * Nn, 256>>>(adj, pmask);

    // 1) question layer
    question_kernel<<<1, 512>>>(qe, wq, Wqc, bqc, pqemb, pqproj);

    // 2) gate: t = x @ Wc^T (fp32 in), then elementwise gate -> f16 activations
    mma_gemm_nt<<<dim3(Dd / 128, Nn / 128, 1), 256>>>(x, Wc, pt, Nn, Dd, Dd);
    gate_kernel<<<Nn, 256>>>(x, pt, bc, pqemb, (unsigned*)pxh);

    // 3) encoder: 2 heads, LN + max
    for (int h = 0; h < 2; ++h) {
        mma_gemm_h<1><<<dim3(Dd / 128, Nn / 128, Rr), 256>>>(
            pxh, pw16 + (long)h * Rr * Dd * Dd, pWhh, Nn, Dd, Dd,
            0, (long)Dd * Dd, (long)Nn * Dd);
        f12_kernel<<<Rr * Nn, 256>>>(pWhh, ea1 + h * Rr * Dd, ea2 + h * Rr * Dd, pf1, pf2);
        att_kernel<<<Rr * Nn, 256>>>(pf1, pf2, pmask, patth, pinv);
        mma_gemm_h<0><<<dim3(Dd / 128, Nn / 128, Rr), 256>>>(
            patth, pWhh, pgo, Nn, Dd, Nn,
            (long)Nn * Nn, (long)Nn * Dd, (long)Nn * Dd);
        postproc_kernel<<<Nn, 256>>>(pgo, (unsigned*)pxh, (h == 1) ? pxenc : nullptr,
                                     lng, lnb, pinv, 1);
    }

    // 4) decoder: 2 heads, LN only on first, final fp32 straight to output
    float* xdout = (out_size >= 5 + Nn * Dd) ? (out + 5) : pxenc;
    for (int i = 0; i < 2; ++i) {
        mma_gemm_h<1><<<dim3(Dd / 128, Nn / 128, Rr), 256>>>(
            pxh, pw16 + WSZ + (long)i * Rr * Dd * Dd, pWhh, Nn, Dd, Dd,
            0, (long)Dd * Dd, (long)Nn * Dd);
        f12_kernel<<<Rr * Nn, 256>>>(pWhh, da1 + i * Rr * Dd, da2 + i * Rr * Dd, pf1, pf2);
        att_kernel<<<Rr * Nn, 256>>>(pf1, pf2, pmask, patth, pinv);
        mma_gemm_h<0><<<dim3(Dd / 128, Nn / 128, Rr), 256>>>(
            patth, pWhh, pgo, Nn, Dd, Nn,
            (long)Nn * Nn, (long)Nn * Dd, (long)Nn * Dd);
        postproc_kernel<<<Nn, 256>>>(pgo,
                                     (i == 0) ? (unsigned*)pxh : nullptr,
                                     (i == 1) ? xdout : nullptr,
                                     lng, lnb, pinv, (i == 0) ? 1 : 0);
    }

    // 5) choice layer -> out[0..4]
    choice_kernel<<<1, 512>>>(pxenc, cidx, pqproj, Wout, bout, out);
}